// round 15
// baseline (speedup 1.0000x reference)
#include <cuda_runtime.h>
#include <cuda_fp16.h>
#include <math.h>
#include <stdint.h>

#define SEQ  8192
#define DIN  512
#define DOUT 64

#define BM 64                  // Q rows per CTA (flash)
#define BN 64                  // keys per tile
#define NTG 64                 // tiles per group (128 total / 2 groups)
#define WQ 68                  // Q/x stage stride (floats)
#define HS 72                  // half-tile stride (halves) -> 144B, conflict-free

// (1/sqrt(64)) * log2(e) folded into Q
#define SCALE2 0.18033688011112042f

// flash smem layout (bytes)
#define QS_OFF   0                       // 64 x WQ floats = 17408
#define GB_OFF   17408
#define GKH(g,b) (GB_OFF + (g) * 55296 + (b) * 27648)
#define GKL(g,b) (GKH(g,b) + 9216)
#define GVT(g,b) (GKH(g,b) + 18432)
#define MA_OFF   128000                  // 192 floats
#define LA_OFF   128768                  // 192 floats
#define SM_TOTAL 129536

// proj smem layout (bytes): x fp32 [2], wh [2], wl [2]
#define PX_OFF(b) ((b) * 17408)          // 64 x WQ floats
#define PW_H(b)  (34816 + (b) * 9216)
#define PW_L(b)  (53248 + (b) * 9216)
#define PSM_TOTAL 71680

// ---------------- scratch ----------------
__device__ float  g_Q[SEQ * DOUT];
__device__ __half g_Kh[SEQ * DOUT];      // fp16 hi part of K  [seq][64]
__device__ __half g_Kl[SEQ * DOUT];      // fp16 lo part of K  [seq][64]
__device__ __half g_VT[DOUT * SEQ];      // fp16 V transposed  [d][seq]
__device__ __half g_WTh[3 * DOUT * DIN]; // fp16 hi of W^T [mat][n][k]
__device__ __half g_WTl[3 * DOUT * DIN]; // fp16 lo of W^T

// ---------------- helpers ----------------
__device__ __forceinline__ float ex2(float x) {
    float r;
    asm("ex2.approx.f32 %0, %1;" : "=f"(r) : "f"(x));
    return r;
}
__device__ __forceinline__ void hmma16(float d[4], uint32_t a0, uint32_t a1,
                                       uint32_t a2, uint32_t a3,
                                       uint32_t b0, uint32_t b1) {
    asm volatile(
        "mma.sync.aligned.m16n8k16.row.col.f32.f16.f16.f32 "
        "{%0,%1,%2,%3}, {%4,%5,%6,%7}, {%8,%9}, {%0,%1,%2,%3};"
        : "+f"(d[0]), "+f"(d[1]), "+f"(d[2]), "+f"(d[3])
        : "r"(a0), "r"(a1), "r"(a2), "r"(a3), "r"(b0), "r"(b1));
}
__device__ __forceinline__ void ldsm_x4(uint32_t& r0, uint32_t& r1,
                                        uint32_t& r2, uint32_t& r3,
                                        const void* p) {
    uint32_t a = (uint32_t)__cvta_generic_to_shared(p);
    asm volatile("ldmatrix.sync.aligned.m8n8.x4.shared.b16 {%0,%1,%2,%3}, [%4];"
                 : "=r"(r0), "=r"(r1), "=r"(r2), "=r"(r3) : "r"(a));
}
__device__ __forceinline__ void cp16(void* dst, const void* src) {
    uint32_t d = (uint32_t)__cvta_generic_to_shared(dst);
    asm volatile("cp.async.cg.shared.global [%0], [%1], 16;" :: "r"(d), "l"(src));
}
#define CP_COMMIT() asm volatile("cp.async.commit_group;" ::: "memory")
#define CP_WAIT(n)  asm volatile("cp.async.wait_group %0;" :: "n"(n) : "memory")
#define BAR_GRP(id) asm volatile("bar.sync %0, 256;" :: "r"(id) : "memory")

// split a pair of fp32 into packed hi/lo half2
__device__ __forceinline__ void pair_split(float x0, float x1,
                                           uint32_t& h, uint32_t& l) {
    __half2 hh = __floats2half2_rn(x0, x1);
    float2 hf = __half22float2(hh);
    __half2 ll = __floats2half2_rn(x0 - hf.x, x1 - hf.y);
    h = *(uint32_t*)&hh;
    l = *(uint32_t*)&ll;
}

// ---------------------------------------------------------------------------
// Kernel 0: W -> W^T (hi, lo) fp16 via smem transpose. grid=24, block=256.
// ---------------------------------------------------------------------------
__global__ __launch_bounds__(256)
void conv_kernel(const float* __restrict__ wq,
                 const float* __restrict__ wk,
                 const float* __restrict__ wv)
{
    __shared__ float ws[64 * 65];
    int wb  = blockIdx.x;                     // 0..23
    int mat = wb >> 3;
    int k0  = (wb & 7) * 64;
    const float* Wm = (mat == 0) ? wq : (mat == 1) ? wk : wv;

    int kr = threadIdx.x >> 2, c4 = threadIdx.x & 3;
    #pragma unroll
    for (int j = 0; j < 4; ++j) {
        float4 v = *(const float4*)&Wm[(k0 + kr) * DOUT + (c4 * 4 + j) * 4];
        float* p = &ws[kr * 65 + (c4 * 4 + j) * 4];
        p[0] = v.x; p[1] = v.y; p[2] = v.z; p[3] = v.w;
    }
    __syncthreads();

    int n = threadIdx.x >> 2, q = threadIdx.x & 3;
    __half hb[16], lb[16];
    #pragma unroll
    for (int j = 0; j < 16; ++j) {
        float v = ws[(q * 16 + j) * 65 + n];
        __half h = __float2half_rn(v);
        hb[j] = h;
        lb[j] = __float2half_rn(v - __half2float(h));
    }
    size_t off = (size_t)(mat * DOUT + n) * DIN + k0 + q * 16;
    *(int4*)&g_WTh[off]     = *(int4*)&hb[0];
    *(int4*)&g_WTh[off + 8] = *(int4*)&hb[8];
    *(int4*)&g_WTl[off]     = *(int4*)&lb[0];
    *(int4*)&g_WTl[off + 8] = *(int4*)&lb[8];
}

// ---------------------------------------------------------------------------
// Kernel 1: QKV projection, fp16 3-pass HMMA, x split inline. grid=(128,3).
// ---------------------------------------------------------------------------
__device__ __forceinline__ void proj_load(char* smb, const float* x, int row0,
                                          int mat, int kc0, int b, int tid) {
    float*  xs = (float*)(smb + PX_OFF(b));
    __half* wh = (__half*)(smb + PW_H(b));
    __half* wl = (__half*)(smb + PW_L(b));
    const __half* wthg = g_WTh + (size_t)mat * DOUT * DIN;
    const __half* wtlg = g_WTl + (size_t)mat * DOUT * DIN;
    #pragma unroll
    for (int it = 0; it < 4; ++it) {
        int idx = it * 256 + tid;         // 0..1023 float4 chunks
        int r = idx >> 4, c4 = idx & 15;
        cp16(&xs[r * WQ + c4 * 4], &x[(size_t)(row0 + r) * DIN + kc0 + c4 * 4]);
    }
    #pragma unroll
    for (int it = 0; it < 2; ++it) {
        int idx = it * 256 + tid;         // 0..511
        int r = idx >> 3, c8 = idx & 7;
        cp16(&wh[r * HS + c8 * 8], &wthg[(size_t)r * DIN + kc0 + c8 * 8]);
        cp16(&wl[r * HS + c8 * 8], &wtlg[(size_t)r * DIN + kc0 + c8 * 8]);
    }
}

__global__ __launch_bounds__(256)
void proj_kernel(const float* __restrict__ x)
{
    extern __shared__ char smb[];
    const int tid   = threadIdx.x;
    const int lane  = tid & 31;
    const int wid   = tid >> 5;
    const int mrow  = wid & 3;
    const int nhalf = wid >> 2;
    const int lq    = lane >> 2;
    const int lr    = lane & 3;
    const int row0  = blockIdx.x * 64;
    const int mat   = blockIdx.y;
    const int r0    = mrow * 16 + lq;

    proj_load(smb, x, row0, mat, 0, 0, tid);
    CP_COMMIT();

    float acc[4][4] = {};

    #pragma unroll 1
    for (int c = 0; c < DIN / 64; ++c) {
        const int b = c & 1;
        CP_WAIT(0);
        __syncthreads();
        if (c + 1 < DIN / 64) {
            proj_load(smb, x, row0, mat, (c + 1) * 64, b ^ 1, tid);
            CP_COMMIT();
        }

        const float*  xs = (const float*)(smb + PX_OFF(b));
        const __half* wh = (const __half*)(smb + PW_H(b));
        const __half* wl = (const __half*)(smb + PW_L(b));

        uint32_t ah[4][4], al[4][4];
        #pragma unroll
        for (int kc = 0; kc < 4; ++kc) {
            int cc = kc * 16 + 2 * lr;
            pair_split(xs[r0 * WQ + cc],           xs[r0 * WQ + cc + 1],
                       ah[kc][0], al[kc][0]);
            pair_split(xs[(r0 + 8) * WQ + cc],     xs[(r0 + 8) * WQ + cc + 1],
                       ah[kc][1], al[kc][1]);
            pair_split(xs[r0 * WQ + cc + 8],       xs[r0 * WQ + cc + 9],
                       ah[kc][2], al[kc][2]);
            pair_split(xs[(r0 + 8) * WQ + cc + 8], xs[(r0 + 8) * WQ + cc + 9],
                       ah[kc][3], al[kc][3]);
        }

        #pragma unroll
        for (int nt = 0; nt < 4; ++nt) {
            const int n = nhalf * 32 + nt * 8 + lq;
            #pragma unroll
            for (int kc = 0; kc < 4; ++kc) {
                const __half* bh = wh + n * HS + kc * 16 + 2 * lr;
                const __half* bl = wl + n * HS + kc * 16 + 2 * lr;
                uint32_t bh0 = *(const uint32_t*)bh;
                uint32_t bh1 = *(const uint32_t*)(bh + 8);
                uint32_t bl0 = *(const uint32_t*)bl;
                uint32_t bl1 = *(const uint32_t*)(bl + 8);
                hmma16(acc[nt], ah[kc][0], ah[kc][1], ah[kc][2], ah[kc][3], bh0, bh1);
                hmma16(acc[nt], al[kc][0], al[kc][1], al[kc][2], al[kc][3], bh0, bh1);
                hmma16(acc[nt], ah[kc][0], ah[kc][1], ah[kc][2], ah[kc][3], bl0, bl1);
            }
        }
    }

    const int rg = row0 + r0;
    if (mat == 0) {
        #pragma unroll
        for (int nt = 0; nt < 4; ++nt) {
            int cc = nhalf * 32 + nt * 8 + 2 * lr;
            *(float2*)&g_Q[(size_t)rg * DOUT + cc]       = make_float2(acc[nt][0], acc[nt][1]);
            *(float2*)&g_Q[(size_t)(rg + 8) * DOUT + cc] = make_float2(acc[nt][2], acc[nt][3]);
        }
    } else if (mat == 1) {
        #pragma unroll
        for (int nt = 0; nt < 4; ++nt) {
            int cc = nhalf * 32 + nt * 8 + 2 * lr;
            uint32_t h0, l0, h1, l1;
            pair_split(acc[nt][0], acc[nt][1], h0, l0);
            pair_split(acc[nt][2], acc[nt][3], h1, l1);
            *(uint32_t*)&g_Kh[(size_t)rg * DOUT + cc]       = h0;
            *(uint32_t*)&g_Kl[(size_t)rg * DOUT + cc]       = l0;
            *(uint32_t*)&g_Kh[(size_t)(rg + 8) * DOUT + cc] = h1;
            *(uint32_t*)&g_Kl[(size_t)(rg + 8) * DOUT + cc] = l1;
        }
    } else {
        #pragma unroll
        for (int nt = 0; nt < 4; ++nt) {
            int cc = nhalf * 32 + nt * 8 + 2 * lr;
            g_VT[(size_t)cc * SEQ + rg]           = __float2half_rn(acc[nt][0]);
            g_VT[(size_t)(cc + 1) * SEQ + rg]     = __float2half_rn(acc[nt][1]);
            g_VT[(size_t)cc * SEQ + rg + 8]       = __float2half_rn(acc[nt][2]);
            g_VT[(size_t)(cc + 1) * SEQ + rg + 8] = __float2half_rn(acc[nt][3]);
        }
    }
}

// ---------------------------------------------------------------------------
// Kernel 2: flash attention, fp16 HMMA + ldmatrix, TWO staggered warp-groups.
// First TWO PV V-fragment pairs preloaded before the softmax (latency hiding).
// ---------------------------------------------------------------------------
__device__ __forceinline__ void load_tile_g(char* smb, int tile, int g, int b,
                                            int gtid) {
    __half* kh = (__half*)(smb + GKH(g, b));
    __half* kl = (__half*)(smb + GKL(g, b));
    __half* vt = (__half*)(smb + GVT(g, b));
    #pragma unroll
    for (int i = 0; i < 2; ++i) {
        int idx = i * 256 + gtid;         // 0..511
        int r = idx >> 3, c8 = idx & 7;
        cp16(&kh[r * HS + c8 * 8], &g_Kh[(size_t)(tile * 64 + r) * DOUT + c8 * 8]);
        cp16(&kl[r * HS + c8 * 8], &g_Kl[(size_t)(tile * 64 + r) * DOUT + c8 * 8]);
        cp16(&vt[r * HS + c8 * 8], &g_VT[(size_t)r * SEQ + tile * 64 + c8 * 8]);
    }
}

__global__ __launch_bounds__(512, 1)
void flash_kernel(float* __restrict__ out)
{
    extern __shared__ char smb[];
    float* Qs = (float*)(smb + QS_OFF);
    float* mA = (float*)(smb + MA_OFF);
    float* lA = (float*)(smb + LA_OFF);

    const int tid   = threadIdx.x;
    const int lane  = tid & 31;
    const int wid   = tid >> 5;
    const int mrow  = wid & 3;
    const int khalf = (wid >> 2) & 1;
    const int g     = wid >> 3;           // warp group 0/1
    const int gtid  = tid & 255;
    const int kb    = khalf * 32;
    const int lq    = lane >> 2;
    const int lr    = lane & 3;
    const int qrow0 = blockIdx.x * BM;
    const int r0    = mrow * 16 + lq;

    // ldmatrix lane offsets (halves)
    const int sOff0 = (kb + ((lane & 16) >> 1) + (lane & 7)) * HS + (lane & 8);
    const int sOff1 = sOff0 + 16 * HS;
    const int vOff  = (((lane & 16) >> 1) + (lane & 7)) * HS + kb + (lane & 8);

    // group prefetch of its first tile
    load_tile_g(smb, g * NTG, g, 0, gtid);
    CP_COMMIT();

    // stage Q (whole CTA), build fragments
    #pragma unroll
    for (int i = 0; i < 2; ++i) {
        int idx = i * 512 + tid;
        int r = idx >> 4, c4 = idx & 15;
        *(float4*)&Qs[r * WQ + c4 * 4] = *(const float4*)&g_Q[(qrow0 + r) * DOUT + c4 * 4];
    }
    __syncthreads();

    uint32_t qh[4][4], ql[4][4];
    #pragma unroll
    for (int kc = 0; kc < 4; ++kc) {
        int c = kc * 16 + 2 * lr;
        pair_split(Qs[r0 * WQ + c] * SCALE2,           Qs[r0 * WQ + c + 1] * SCALE2,
                   qh[kc][0], ql[kc][0]);
        pair_split(Qs[(r0 + 8) * WQ + c] * SCALE2,     Qs[(r0 + 8) * WQ + c + 1] * SCALE2,
                   qh[kc][1], ql[kc][1]);
        pair_split(Qs[r0 * WQ + c + 8] * SCALE2,       Qs[r0 * WQ + c + 9] * SCALE2,
                   qh[kc][2], ql[kc][2]);
        pair_split(Qs[(r0 + 8) * WQ + c + 8] * SCALE2, Qs[(r0 + 8) * WQ + c + 9] * SCALE2,
                   qh[kc][3], ql[kc][3]);
    }

    float m0 = -INFINITY, m1 = -INFINITY;
    float l0 = 0.f, l1 = 0.f;              // lane-PARTIAL row sums
    float o[8][4];
    #pragma unroll
    for (int i = 0; i < 8; ++i)
        o[i][0] = o[i][1] = o[i][2] = o[i][3] = 0.f;

    #pragma unroll 1
    for (int tl = 0; tl < NTG; ++tl) {
        const int b = tl & 1;
        const __half* kh0 = (const __half*)(smb + GKH(g, b)) + sOff0;
        const __half* kl0 = (const __half*)(smb + GKL(g, b)) + sOff0;
        const __half* kh1 = (const __half*)(smb + GKH(g, b)) + sOff1;
        const __half* kl1 = (const __half*)(smb + GKL(g, b)) + sOff1;
        const __half* vtp = (const __half*)(smb + GVT(g, b)) + vOff;

        CP_WAIT(0);
        BAR_GRP(1 + g);

        if (tl + 1 < NTG) {
            load_tile_g(smb, g * NTG + tl + 1, g, b ^ 1, gtid);
            CP_COMMIT();
        }

        // ---- S = Q K^T over this warp's 32 keys (two 16-key n-groups) ----
        float s[4][4] = {};
        #pragma unroll
        for (int kc = 0; kc < 4; ++kc) {
            uint32_t h0, h1, h2, h3, c0, c1, c2, c3;
            ldsm_x4(h0, h1, h2, h3, kh0 + kc * 16);
            ldsm_x4(c0, c1, c2, c3, kl0 + kc * 16);
            hmma16(s[0], qh[kc][0], qh[kc][1], qh[kc][2], qh[kc][3], h0, h1);
            hmma16(s[0], ql[kc][0], ql[kc][1], ql[kc][2], ql[kc][3], h0, h1);
            hmma16(s[0], qh[kc][0], qh[kc][1], qh[kc][2], qh[kc][3], c0, c1);
            hmma16(s[1], qh[kc][0], qh[kc][1], qh[kc][2], qh[kc][3], h2, h3);
            hmma16(s[1], ql[kc][0], ql[kc][1], ql[kc][2], ql[kc][3], h2, h3);
            hmma16(s[1], qh[kc][0], qh[kc][1], qh[kc][2], qh[kc][3], c2, c3);

            ldsm_x4(h0, h1, h2, h3, kh1 + kc * 16);
            ldsm_x4(c0, c1, c2, c3, kl1 + kc * 16);
            hmma16(s[2], qh[kc][0], qh[kc][1], qh[kc][2], qh[kc][3], h0, h1);
            hmma16(s[2], ql[kc][0], ql[kc][1], ql[kc][2], ql[kc][3], h0, h1);
            hmma16(s[2], qh[kc][0], qh[kc][1], qh[kc][2], qh[kc][3], c0, c1);
            hmma16(s[3], qh[kc][0], qh[kc][1], qh[kc][2], qh[kc][3], h2, h3);
            hmma16(s[3], ql[kc][0], ql[kc][1], ql[kc][2], ql[kc][3], h2, h3);
            hmma16(s[3], qh[kc][0], qh[kc][1], qh[kc][2], qh[kc][3], c2, c3);
        }

        // ---- preload first TWO PV V-fragment pairs (softmax-independent) ----
        uint32_t vb0[4], vb1[4], vb2[4], vb3[4];
        ldsm_x4(vb0[0], vb0[1], vb0[2], vb0[3], vtp);
        ldsm_x4(vb1[0], vb1[1], vb1[2], vb1[3], vtp + 16);
        ldsm_x4(vb2[0], vb2[1], vb2[2], vb2[3], vtp + 16 * HS);
        ldsm_x4(vb3[0], vb3[1], vb3[2], vb3[3], vtp + 16 * HS + 16);

        // ---- warp-local online softmax over 32 keys ----
        float mx0 = fmaxf(fmaxf(s[0][0], s[0][1]), fmaxf(s[1][0], s[1][1]));
        float mx1 = fmaxf(fmaxf(s[0][2], s[0][3]), fmaxf(s[1][2], s[1][3]));
        mx0 = fmaxf(mx0, fmaxf(fmaxf(s[2][0], s[2][1]), fmaxf(s[3][0], s[3][1])));
        mx1 = fmaxf(mx1, fmaxf(fmaxf(s[2][2], s[2][3]), fmaxf(s[3][2], s[3][3])));
        mx0 = fmaxf(mx0, __shfl_xor_sync(0xffffffffu, mx0, 1));
        mx0 = fmaxf(mx0, __shfl_xor_sync(0xffffffffu, mx0, 2));
        mx1 = fmaxf(mx1, __shfl_xor_sync(0xffffffffu, mx1, 1));
        mx1 = fmaxf(mx1, __shfl_xor_sync(0xffffffffu, mx1, 2));

        float nm0 = fmaxf(m0, mx0), nm1 = fmaxf(m1, mx1);
        float cr0 = ex2(m0 - nm0),  cr1 = ex2(m1 - nm1);
        m0 = nm0; m1 = nm1;

        uint32_t Apk[2][4];
        float ps0 = 0.f, ps1 = 0.f;
        #pragma unroll
        for (int gg = 0; gg < 2; ++gg) {
            float p00 = ex2(s[2*gg][0] - nm0), p01 = ex2(s[2*gg][1] - nm0);
            float p02 = ex2(s[2*gg][2] - nm1), p03 = ex2(s[2*gg][3] - nm1);
            float p10 = ex2(s[2*gg+1][0] - nm0), p11 = ex2(s[2*gg+1][1] - nm0);
            float p12 = ex2(s[2*gg+1][2] - nm1), p13 = ex2(s[2*gg+1][3] - nm1);
            __half2 A0 = __floats2half2_rn(p00, p01);
            __half2 A1 = __floats2half2_rn(p02, p03);
            __half2 A2 = __floats2half2_rn(p10, p11);
            __half2 A3 = __floats2half2_rn(p12, p13);
            float2 f0 = __half22float2(A0), f1 = __half22float2(A1);
            float2 f2 = __half22float2(A2), f3 = __half22float2(A3);
            ps0 += f0.x + f0.y + f2.x + f2.y;
            ps1 += f1.x + f1.y + f3.x + f3.y;
            Apk[gg][0] = *(uint32_t*)&A0;
            Apk[gg][1] = *(uint32_t*)&A1;
            Apk[gg][2] = *(uint32_t*)&A2;
            Apk[gg][3] = *(uint32_t*)&A3;
        }
        l0 = l0 * cr0 + ps0;
        l1 = l1 * cr1 + ps1;

        if (__any_sync(0xffffffffu,
                       (__float_as_uint(cr0) != 0x3f800000u) |
                       (__float_as_uint(cr1) != 0x3f800000u))) {
            #pragma unroll
            for (int nd = 0; nd < 8; ++nd) {
                o[nd][0] *= cr0; o[nd][1] *= cr0;
                o[nd][2] *= cr1; o[nd][3] *= cr1;
            }
        }

        // ---- O_partial += P @ V over 32 keys (two k16 chunks) ----
        // ndp = 0,1 use the preloaded fragments
        hmma16(o[0], Apk[0][0], Apk[0][1], Apk[0][2], Apk[0][3], vb0[0], vb0[1]);
        hmma16(o[1], Apk[0][0], Apk[0][1], Apk[0][2], Apk[0][3], vb0[2], vb0[3]);
        hmma16(o[0], Apk[1][0], Apk[1][1], Apk[1][2], Apk[1][3], vb1[0], vb1[1]);
        hmma16(o[1], Apk[1][0], Apk[1][1], Apk[1][2], Apk[1][3], vb1[2], vb1[3]);
        hmma16(o[2], Apk[0][0], Apk[0][1], Apk[0][2], Apk[0][3], vb2[0], vb2[1]);
        hmma16(o[3], Apk[0][0], Apk[0][1], Apk[0][2], Apk[0][3], vb2[2], vb2[3]);
        hmma16(o[2], Apk[1][0], Apk[1][1], Apk[1][2], Apk[1][3], vb3[0], vb3[1]);
        hmma16(o[3], Apk[1][0], Apk[1][1], Apk[1][2], Apk[1][3], vb3[2], vb3[3]);
        #pragma unroll
        for (int ndp = 2; ndp < 4; ++ndp) {
            uint32_t b0, b1, b2, b3;
            ldsm_x4(b0, b1, b2, b3, vtp + ndp * 16 * HS);
            hmma16(o[2 * ndp],     Apk[0][0], Apk[0][1], Apk[0][2], Apk[0][3], b0, b1);
            hmma16(o[2 * ndp + 1], Apk[0][0], Apk[0][1], Apk[0][2], Apk[0][3], b2, b3);
            ldsm_x4(b0, b1, b2, b3, vtp + ndp * 16 * HS + 16);
            hmma16(o[2 * ndp],     Apk[1][0], Apk[1][1], Apk[1][2], Apk[1][3], b0, b1);
            hmma16(o[2 * ndp + 1], Apk[1][0], Apk[1][1], Apk[1][2], Apk[1][3], b2, b3);
        }
    }

    // lane-reduce the deferred l partials (once)
    l0 += __shfl_xor_sync(0xffffffffu, l0, 1);
    l0 += __shfl_xor_sync(0xffffffffu, l0, 2);
    l1 += __shfl_xor_sync(0xffffffffu, l1, 1);
    l1 += __shfl_xor_sync(0xffffffffu, l1, 2);

    // ---- epilogue: merge 4 partials per row (2 groups x 2 key-halves) ----
    __syncthreads();   // full-CTA: both groups done with their buffers
    const int p = g * 2 + khalf;               // partial index 0..3
    float* R1 = (float*)(smb + QS_OFF);
    float* R2 = (float*)(smb + GB_OFF);
    float* R3 = (float*)(smb + GB_OFF + 16384);
    float* Rs[3] = { R1, R2, R3 };

    if (p > 0) {
        float* Rb = Rs[p - 1];
        if (lr == 0) {
            mA[(p - 1) * 64 + r0]     = m0;  mA[(p - 1) * 64 + r0 + 8] = m1;
            lA[(p - 1) * 64 + r0]     = l0;  lA[(p - 1) * 64 + r0 + 8] = l1;
        }
        #pragma unroll
        for (int nd = 0; nd < 8; ++nd) {
            *(float2*)&Rb[r0 * 64 + nd * 8 + 2 * lr]       = make_float2(o[nd][0], o[nd][1]);
            *(float2*)&Rb[(r0 + 8) * 64 + nd * 8 + 2 * lr] = make_float2(o[nd][2], o[nd][3]);
        }
    }
    __syncthreads();
    if (p == 0) {
        float M0 = m0, M1 = m1;
        #pragma unroll
        for (int i = 0; i < 3; ++i) {
            M0 = fmaxf(M0, mA[i * 64 + r0]);
            M1 = fmaxf(M1, mA[i * 64 + r0 + 8]);
        }
        float w0 = ex2(m0 - M0), w1 = ex2(m1 - M1);
        float L0 = l0 * w0, L1 = l1 * w1;
        float acc0[8][2], acc1[8][2];
        #pragma unroll
        for (int nd = 0; nd < 8; ++nd) {
            acc0[nd][0] = o[nd][0] * w0; acc0[nd][1] = o[nd][1] * w0;
            acc1[nd][0] = o[nd][2] * w1; acc1[nd][1] = o[nd][3] * w1;
        }
        #pragma unroll
        for (int i = 0; i < 3; ++i) {
            float u0 = ex2(mA[i * 64 + r0]     - M0);
            float u1 = ex2(mA[i * 64 + r0 + 8] - M1);
            L0 += lA[i * 64 + r0]     * u0;
            L1 += lA[i * 64 + r0 + 8] * u1;
            const float* Rb = Rs[i];
            #pragma unroll
            for (int nd = 0; nd < 8; ++nd) {
                float2 p0 = *(const float2*)&Rb[r0 * 64 + nd * 8 + 2 * lr];
                float2 p1 = *(const float2*)&Rb[(r0 + 8) * 64 + nd * 8 + 2 * lr];
                acc0[nd][0] += p0.x * u0; acc0[nd][1] += p0.y * u0;
                acc1[nd][0] += p1.x * u1; acc1[nd][1] += p1.y * u1;
            }
        }
        float il0 = 1.0f / L0, il1 = 1.0f / L1;
        int row = qrow0 + r0;
        #pragma unroll
        for (int nd = 0; nd < 8; ++nd) {
            *(float2*)&out[row * DOUT + nd * 8 + 2 * lr] =
                make_float2(acc0[nd][0] * il0, acc0[nd][1] * il0);
            *(float2*)&out[(row + 8) * DOUT + nd * 8 + 2 * lr] =
                make_float2(acc1[nd][0] * il1, acc1[nd][1] * il1);
        }
    }
}

// ---------------------------------------------------------------------------
extern "C" void kernel_launch(void* const* d_in, const int* in_sizes, int n_in,
                              void* d_out, int out_size)
{
    (void)in_sizes; (void)n_in; (void)out_size;
    const float* x  = (const float*)d_in[0];
    const float* wq = (const float*)d_in[1];
    const float* wk = (const float*)d_in[2];
    const float* wv = (const float*)d_in[3];
    float* out      = (float*)d_out;

    cudaFuncSetAttribute(proj_kernel,  cudaFuncAttributeMaxDynamicSharedMemorySize, PSM_TOTAL);
    cudaFuncSetAttribute(flash_kernel, cudaFuncAttributeMaxDynamicSharedMemorySize, SM_TOTAL);

    conv_kernel<<<24, 256>>>(wq, wk, wv);
    proj_kernel<<<dim3(SEQ / 64, 3), 256, PSM_TOTAL>>>(x);
    flash_kernel<<<SEQ / BM, 512, SM_TOTAL>>>(out);
}

// round 16
// speedup vs baseline: 1.0763x; 1.0763x over previous
#include <cuda_runtime.h>
#include <cuda_fp16.h>
#include <math.h>
#include <stdint.h>

#define SEQ  8192
#define DIN  512
#define DOUT 64

#define BM 64                  // Q rows per CTA (flash)
#define BN 64                  // keys per tile
#define NTG 64                 // tiles per group (128 total / 2 groups)
#define WQ 68                  // Q/x stage stride (floats)
#define HS 72                  // half-tile stride (halves) -> 144B, conflict-free

// (1/sqrt(64)) * log2(e) folded into Q
#define SCALE2 0.18033688011112042f

// flash smem layout (bytes)
#define QS_OFF   0                       // 64 x WQ floats = 17408
#define GB_OFF   17408
#define GKH(g,b) (GB_OFF + (g) * 55296 + (b) * 27648)
#define GKL(g,b) (GKH(g,b) + 9216)
#define GVT(g,b) (GKH(g,b) + 18432)
#define MA_OFF   128000                  // 192 floats
#define LA_OFF   128768                  // 192 floats
#define SM_TOTAL 129536

// proj smem layout (bytes): x fp32 [2], wh [2], wl [2]
#define PX_OFF(b) ((b) * 17408)          // 64 x WQ floats
#define PW_H(b)  (34816 + (b) * 9216)
#define PW_L(b)  (53248 + (b) * 9216)
#define PSM_TOTAL 71680

// ---------------- scratch ----------------
__device__ float  g_Q[SEQ * DOUT];
__device__ __half g_Kh[SEQ * DOUT];      // fp16 hi part of K  [seq][64]
__device__ __half g_Kl[SEQ * DOUT];      // fp16 lo part of K  [seq][64]
__device__ __half g_VT[DOUT * SEQ];      // fp16 V transposed  [d][seq]
__device__ __half g_WTh[3 * DOUT * DIN]; // fp16 hi of W^T [mat][n][k]
__device__ __half g_WTl[3 * DOUT * DIN]; // fp16 lo of W^T

// ---------------- helpers ----------------
__device__ __forceinline__ float ex2(float x) {
    float r;
    asm("ex2.approx.f32 %0, %1;" : "=f"(r) : "f"(x));
    return r;
}
__device__ __forceinline__ void hmma16(float d[4], uint32_t a0, uint32_t a1,
                                       uint32_t a2, uint32_t a3,
                                       uint32_t b0, uint32_t b1) {
    asm volatile(
        "mma.sync.aligned.m16n8k16.row.col.f32.f16.f16.f32 "
        "{%0,%1,%2,%3}, {%4,%5,%6,%7}, {%8,%9}, {%0,%1,%2,%3};"
        : "+f"(d[0]), "+f"(d[1]), "+f"(d[2]), "+f"(d[3])
        : "r"(a0), "r"(a1), "r"(a2), "r"(a3), "r"(b0), "r"(b1));
}
__device__ __forceinline__ void ldsm_x4(uint32_t& r0, uint32_t& r1,
                                        uint32_t& r2, uint32_t& r3,
                                        const void* p) {
    uint32_t a = (uint32_t)__cvta_generic_to_shared(p);
    asm volatile("ldmatrix.sync.aligned.m8n8.x4.shared.b16 {%0,%1,%2,%3}, [%4];"
                 : "=r"(r0), "=r"(r1), "=r"(r2), "=r"(r3) : "r"(a));
}
__device__ __forceinline__ void cp16(void* dst, const void* src) {
    uint32_t d = (uint32_t)__cvta_generic_to_shared(dst);
    asm volatile("cp.async.cg.shared.global [%0], [%1], 16;" :: "r"(d), "l"(src));
}
#define CP_COMMIT() asm volatile("cp.async.commit_group;" ::: "memory")
#define CP_WAIT(n)  asm volatile("cp.async.wait_group %0;" :: "n"(n) : "memory")
#define BAR_GRP(id) asm volatile("bar.sync %0, 256;" :: "r"(id) : "memory")

// split a pair of fp32 into packed hi/lo half2
__device__ __forceinline__ void pair_split(float x0, float x1,
                                           uint32_t& h, uint32_t& l) {
    __half2 hh = __floats2half2_rn(x0, x1);
    float2 hf = __half22float2(hh);
    __half2 ll = __floats2half2_rn(x0 - hf.x, x1 - hf.y);
    h = *(uint32_t*)&hh;
    l = *(uint32_t*)&ll;
}

// ---------------------------------------------------------------------------
// Kernel 0: W -> W^T (hi, lo) fp16 via smem transpose. grid=24, block=256.
// ---------------------------------------------------------------------------
__global__ __launch_bounds__(256)
void conv_kernel(const float* __restrict__ wq,
                 const float* __restrict__ wk,
                 const float* __restrict__ wv)
{
    __shared__ float ws[64 * 65];
    int wb  = blockIdx.x;                     // 0..23
    int mat = wb >> 3;
    int k0  = (wb & 7) * 64;
    const float* Wm = (mat == 0) ? wq : (mat == 1) ? wk : wv;

    int kr = threadIdx.x >> 2, c4 = threadIdx.x & 3;
    #pragma unroll
    for (int j = 0; j < 4; ++j) {
        float4 v = *(const float4*)&Wm[(k0 + kr) * DOUT + (c4 * 4 + j) * 4];
        float* p = &ws[kr * 65 + (c4 * 4 + j) * 4];
        p[0] = v.x; p[1] = v.y; p[2] = v.z; p[3] = v.w;
    }
    __syncthreads();

    int n = threadIdx.x >> 2, q = threadIdx.x & 3;
    __half hb[16], lb[16];
    #pragma unroll
    for (int j = 0; j < 16; ++j) {
        float v = ws[(q * 16 + j) * 65 + n];
        __half h = __float2half_rn(v);
        hb[j] = h;
        lb[j] = __float2half_rn(v - __half2float(h));
    }
    size_t off = (size_t)(mat * DOUT + n) * DIN + k0 + q * 16;
    *(int4*)&g_WTh[off]     = *(int4*)&hb[0];
    *(int4*)&g_WTh[off + 8] = *(int4*)&hb[8];
    *(int4*)&g_WTl[off]     = *(int4*)&lb[0];
    *(int4*)&g_WTl[off + 8] = *(int4*)&lb[8];
}

// ---------------------------------------------------------------------------
// Kernel 1: QKV projection, fp16 3-pass HMMA, x split inline, W via ldmatrix.
// grid=(128,3), block=256.
// ---------------------------------------------------------------------------
__device__ __forceinline__ void proj_load(char* smb, const float* x, int row0,
                                          int mat, int kc0, int b, int tid) {
    float*  xs = (float*)(smb + PX_OFF(b));
    __half* wh = (__half*)(smb + PW_H(b));
    __half* wl = (__half*)(smb + PW_L(b));
    const __half* wthg = g_WTh + (size_t)mat * DOUT * DIN;
    const __half* wtlg = g_WTl + (size_t)mat * DOUT * DIN;
    #pragma unroll
    for (int it = 0; it < 4; ++it) {
        int idx = it * 256 + tid;         // 0..1023 float4 chunks
        int r = idx >> 4, c4 = idx & 15;
        cp16(&xs[r * WQ + c4 * 4], &x[(size_t)(row0 + r) * DIN + kc0 + c4 * 4]);
    }
    #pragma unroll
    for (int it = 0; it < 2; ++it) {
        int idx = it * 256 + tid;         // 0..511
        int r = idx >> 3, c8 = idx & 7;
        cp16(&wh[r * HS + c8 * 8], &wthg[(size_t)r * DIN + kc0 + c8 * 8]);
        cp16(&wl[r * HS + c8 * 8], &wtlg[(size_t)r * DIN + kc0 + c8 * 8]);
    }
}

__global__ __launch_bounds__(256)
void proj_kernel(const float* __restrict__ x)
{
    extern __shared__ char smb[];
    const int tid   = threadIdx.x;
    const int lane  = tid & 31;
    const int wid   = tid >> 5;
    const int mrow  = wid & 3;
    const int nhalf = wid >> 2;
    const int lq    = lane >> 2;
    const int lr    = lane & 3;
    const int row0  = blockIdx.x * 64;
    const int mat   = blockIdx.y;
    const int r0    = mrow * 16 + lq;

    // ldmatrix lane offsets for W fragments (rows nhalf*32 .. +31)
    const int wOff0 = (nhalf * 32 + ((lane & 16) >> 1) + (lane & 7)) * HS + (lane & 8);
    const int wOff1 = wOff0 + 16 * HS;

    proj_load(smb, x, row0, mat, 0, 0, tid);
    CP_COMMIT();

    float acc[4][4] = {};

    #pragma unroll 1
    for (int c = 0; c < DIN / 64; ++c) {
        const int b = c & 1;
        CP_WAIT(0);
        __syncthreads();
        if (c + 1 < DIN / 64) {
            proj_load(smb, x, row0, mat, (c + 1) * 64, b ^ 1, tid);
            CP_COMMIT();
        }

        const float*  xs  = (const float*)(smb + PX_OFF(b));
        const __half* wh0 = (const __half*)(smb + PW_H(b)) + wOff0;
        const __half* wh1 = (const __half*)(smb + PW_H(b)) + wOff1;
        const __half* wl0 = (const __half*)(smb + PW_L(b)) + wOff0;
        const __half* wl1 = (const __half*)(smb + PW_L(b)) + wOff1;

        uint32_t ah[4][4], al[4][4];
        #pragma unroll
        for (int kc = 0; kc < 4; ++kc) {
            int cc = kc * 16 + 2 * lr;
            pair_split(xs[r0 * WQ + cc],           xs[r0 * WQ + cc + 1],
                       ah[kc][0], al[kc][0]);
            pair_split(xs[(r0 + 8) * WQ + cc],     xs[(r0 + 8) * WQ + cc + 1],
                       ah[kc][1], al[kc][1]);
            pair_split(xs[r0 * WQ + cc + 8],       xs[r0 * WQ + cc + 9],
                       ah[kc][2], al[kc][2]);
            pair_split(xs[(r0 + 8) * WQ + cc + 8], xs[(r0 + 8) * WQ + cc + 9],
                       ah[kc][3], al[kc][3]);
        }

        #pragma unroll
        for (int kc = 0; kc < 4; ++kc) {
            uint32_t b0, b1, b2, b3, c0, c1, c2, c3;
            ldsm_x4(b0, b1, b2, b3, wh0 + kc * 16);
            ldsm_x4(c0, c1, c2, c3, wl0 + kc * 16);
            hmma16(acc[0], ah[kc][0], ah[kc][1], ah[kc][2], ah[kc][3], b0, b1);
            hmma16(acc[0], al[kc][0], al[kc][1], al[kc][2], al[kc][3], b0, b1);
            hmma16(acc[0], ah[kc][0], ah[kc][1], ah[kc][2], ah[kc][3], c0, c1);
            hmma16(acc[1], ah[kc][0], ah[kc][1], ah[kc][2], ah[kc][3], b2, b3);
            hmma16(acc[1], al[kc][0], al[kc][1], al[kc][2], al[kc][3], b2, b3);
            hmma16(acc[1], ah[kc][0], ah[kc][1], ah[kc][2], ah[kc][3], c2, c3);

            ldsm_x4(b0, b1, b2, b3, wh1 + kc * 16);
            ldsm_x4(c0, c1, c2, c3, wl1 + kc * 16);
            hmma16(acc[2], ah[kc][0], ah[kc][1], ah[kc][2], ah[kc][3], b0, b1);
            hmma16(acc[2], al[kc][0], al[kc][1], al[kc][2], al[kc][3], b0, b1);
            hmma16(acc[2], ah[kc][0], ah[kc][1], ah[kc][2], ah[kc][3], c0, c1);
            hmma16(acc[3], ah[kc][0], ah[kc][1], ah[kc][2], ah[kc][3], b2, b3);
            hmma16(acc[3], al[kc][0], al[kc][1], al[kc][2], al[kc][3], b2, b3);
            hmma16(acc[3], ah[kc][0], ah[kc][1], ah[kc][2], ah[kc][3], c2, c3);
        }
    }

    const int rg = row0 + r0;
    if (mat == 0) {
        #pragma unroll
        for (int nt = 0; nt < 4; ++nt) {
            int cc = nhalf * 32 + nt * 8 + 2 * lr;
            *(float2*)&g_Q[(size_t)rg * DOUT + cc]       = make_float2(acc[nt][0], acc[nt][1]);
            *(float2*)&g_Q[(size_t)(rg + 8) * DOUT + cc] = make_float2(acc[nt][2], acc[nt][3]);
        }
    } else if (mat == 1) {
        #pragma unroll
        for (int nt = 0; nt < 4; ++nt) {
            int cc = nhalf * 32 + nt * 8 + 2 * lr;
            uint32_t h0, l0, h1, l1;
            pair_split(acc[nt][0], acc[nt][1], h0, l0);
            pair_split(acc[nt][2], acc[nt][3], h1, l1);
            *(uint32_t*)&g_Kh[(size_t)rg * DOUT + cc]       = h0;
            *(uint32_t*)&g_Kl[(size_t)rg * DOUT + cc]       = l0;
            *(uint32_t*)&g_Kh[(size_t)(rg + 8) * DOUT + cc] = h1;
            *(uint32_t*)&g_Kl[(size_t)(rg + 8) * DOUT + cc] = l1;
        }
    } else {
        #pragma unroll
        for (int nt = 0; nt < 4; ++nt) {
            int cc = nhalf * 32 + nt * 8 + 2 * lr;
            g_VT[(size_t)cc * SEQ + rg]           = __float2half_rn(acc[nt][0]);
            g_VT[(size_t)(cc + 1) * SEQ + rg]     = __float2half_rn(acc[nt][1]);
            g_VT[(size_t)cc * SEQ + rg + 8]       = __float2half_rn(acc[nt][2]);
            g_VT[(size_t)(cc + 1) * SEQ + rg + 8] = __float2half_rn(acc[nt][3]);
        }
    }
}

// ---------------------------------------------------------------------------
// Kernel 2: flash attention — R14 structure verbatim (best known: 154.5us).
// Two staggered warp-groups; ONE PV V-fragment pair preloaded before softmax.
// ---------------------------------------------------------------------------
__device__ __forceinline__ void load_tile_g(char* smb, int tile, int g, int b,
                                            int gtid) {
    __half* kh = (__half*)(smb + GKH(g, b));
    __half* kl = (__half*)(smb + GKL(g, b));
    __half* vt = (__half*)(smb + GVT(g, b));
    #pragma unroll
    for (int i = 0; i < 2; ++i) {
        int idx = i * 256 + gtid;         // 0..511
        int r = idx >> 3, c8 = idx & 7;
        cp16(&kh[r * HS + c8 * 8], &g_Kh[(size_t)(tile * 64 + r) * DOUT + c8 * 8]);
        cp16(&kl[r * HS + c8 * 8], &g_Kl[(size_t)(tile * 64 + r) * DOUT + c8 * 8]);
        cp16(&vt[r * HS + c8 * 8], &g_VT[(size_t)r * SEQ + tile * 64 + c8 * 8]);
    }
}

__global__ __launch_bounds__(512, 1)
void flash_kernel(float* __restrict__ out)
{
    extern __shared__ char smb[];
    float* Qs = (float*)(smb + QS_OFF);
    float* mA = (float*)(smb + MA_OFF);
    float* lA = (float*)(smb + LA_OFF);

    const int tid   = threadIdx.x;
    const int lane  = tid & 31;
    const int wid   = tid >> 5;
    const int mrow  = wid & 3;
    const int khalf = (wid >> 2) & 1;
    const int g     = wid >> 3;           // warp group 0/1
    const int gtid  = tid & 255;
    const int kb    = khalf * 32;
    const int lq    = lane >> 2;
    const int lr    = lane & 3;
    const int qrow0 = blockIdx.x * BM;
    const int r0    = mrow * 16 + lq;

    // ldmatrix lane offsets (halves)
    const int sOff0 = (kb + ((lane & 16) >> 1) + (lane & 7)) * HS + (lane & 8);
    const int sOff1 = sOff0 + 16 * HS;
    const int vOff  = (((lane & 16) >> 1) + (lane & 7)) * HS + kb + (lane & 8);

    // group prefetch of its first tile
    load_tile_g(smb, g * NTG, g, 0, gtid);
    CP_COMMIT();

    // stage Q (whole CTA), build fragments
    #pragma unroll
    for (int i = 0; i < 2; ++i) {
        int idx = i * 512 + tid;
        int r = idx >> 4, c4 = idx & 15;
        *(float4*)&Qs[r * WQ + c4 * 4] = *(const float4*)&g_Q[(qrow0 + r) * DOUT + c4 * 4];
    }
    __syncthreads();

    uint32_t qh[4][4], ql[4][4];
    #pragma unroll
    for (int kc = 0; kc < 4; ++kc) {
        int c = kc * 16 + 2 * lr;
        pair_split(Qs[r0 * WQ + c] * SCALE2,           Qs[r0 * WQ + c + 1] * SCALE2,
                   qh[kc][0], ql[kc][0]);
        pair_split(Qs[(r0 + 8) * WQ + c] * SCALE2,     Qs[(r0 + 8) * WQ + c + 1] * SCALE2,
                   qh[kc][1], ql[kc][1]);
        pair_split(Qs[r0 * WQ + c + 8] * SCALE2,       Qs[r0 * WQ + c + 9] * SCALE2,
                   qh[kc][2], ql[kc][2]);
        pair_split(Qs[(r0 + 8) * WQ + c + 8] * SCALE2, Qs[(r0 + 8) * WQ + c + 9] * SCALE2,
                   qh[kc][3], ql[kc][3]);
    }

    float m0 = -INFINITY, m1 = -INFINITY;
    float l0 = 0.f, l1 = 0.f;              // lane-PARTIAL row sums
    float o[8][4];
    #pragma unroll
    for (int i = 0; i < 8; ++i)
        o[i][0] = o[i][1] = o[i][2] = o[i][3] = 0.f;

    #pragma unroll 1
    for (int tl = 0; tl < NTG; ++tl) {
        const int b = tl & 1;
        const __half* kh0 = (const __half*)(smb + GKH(g, b)) + sOff0;
        const __half* kl0 = (const __half*)(smb + GKL(g, b)) + sOff0;
        const __half* kh1 = (const __half*)(smb + GKH(g, b)) + sOff1;
        const __half* kl1 = (const __half*)(smb + GKL(g, b)) + sOff1;
        const __half* vtp = (const __half*)(smb + GVT(g, b)) + vOff;

        CP_WAIT(0);
        BAR_GRP(1 + g);

        if (tl + 1 < NTG) {
            load_tile_g(smb, g * NTG + tl + 1, g, b ^ 1, gtid);
            CP_COMMIT();
        }

        // ---- S = Q K^T over this warp's 32 keys (two 16-key n-groups) ----
        float s[4][4] = {};
        #pragma unroll
        for (int kc = 0; kc < 4; ++kc) {
            uint32_t h0, h1, h2, h3, c0, c1, c2, c3;
            ldsm_x4(h0, h1, h2, h3, kh0 + kc * 16);
            ldsm_x4(c0, c1, c2, c3, kl0 + kc * 16);
            hmma16(s[0], qh[kc][0], qh[kc][1], qh[kc][2], qh[kc][3], h0, h1);
            hmma16(s[0], ql[kc][0], ql[kc][1], ql[kc][2], ql[kc][3], h0, h1);
            hmma16(s[0], qh[kc][0], qh[kc][1], qh[kc][2], qh[kc][3], c0, c1);
            hmma16(s[1], qh[kc][0], qh[kc][1], qh[kc][2], qh[kc][3], h2, h3);
            hmma16(s[1], ql[kc][0], ql[kc][1], ql[kc][2], ql[kc][3], h2, h3);
            hmma16(s[1], qh[kc][0], qh[kc][1], qh[kc][2], qh[kc][3], c2, c3);

            ldsm_x4(h0, h1, h2, h3, kh1 + kc * 16);
            ldsm_x4(c0, c1, c2, c3, kl1 + kc * 16);
            hmma16(s[2], qh[kc][0], qh[kc][1], qh[kc][2], qh[kc][3], h0, h1);
            hmma16(s[2], ql[kc][0], ql[kc][1], ql[kc][2], ql[kc][3], h0, h1);
            hmma16(s[2], qh[kc][0], qh[kc][1], qh[kc][2], qh[kc][3], c0, c1);
            hmma16(s[3], qh[kc][0], qh[kc][1], qh[kc][2], qh[kc][3], h2, h3);
            hmma16(s[3], ql[kc][0], ql[kc][1], ql[kc][2], ql[kc][3], h2, h3);
            hmma16(s[3], qh[kc][0], qh[kc][1], qh[kc][2], qh[kc][3], c2, c3);
        }

        // ---- preload first PV V-fragments (independent of softmax) ----
        uint32_t vb0[4], vb1[4];
        ldsm_x4(vb0[0], vb0[1], vb0[2], vb0[3], vtp);
        ldsm_x4(vb1[0], vb1[1], vb1[2], vb1[3], vtp + 16);

        // ---- warp-local online softmax over 32 keys ----
        float mx0 = fmaxf(fmaxf(s[0][0], s[0][1]), fmaxf(s[1][0], s[1][1]));
        float mx1 = fmaxf(fmaxf(s[0][2], s[0][3]), fmaxf(s[1][2], s[1][3]));
        mx0 = fmaxf(mx0, fmaxf(fmaxf(s[2][0], s[2][1]), fmaxf(s[3][0], s[3][1])));
        mx1 = fmaxf(mx1, fmaxf(fmaxf(s[2][2], s[2][3]), fmaxf(s[3][2], s[3][3])));
        mx0 = fmaxf(mx0, __shfl_xor_sync(0xffffffffu, mx0, 1));
        mx0 = fmaxf(mx0, __shfl_xor_sync(0xffffffffu, mx0, 2));
        mx1 = fmaxf(mx1, __shfl_xor_sync(0xffffffffu, mx1, 1));
        mx1 = fmaxf(mx1, __shfl_xor_sync(0xffffffffu, mx1, 2));

        float nm0 = fmaxf(m0, mx0), nm1 = fmaxf(m1, mx1);
        float cr0 = ex2(m0 - nm0),  cr1 = ex2(m1 - nm1);
        m0 = nm0; m1 = nm1;

        uint32_t Apk[2][4];
        float ps0 = 0.f, ps1 = 0.f;
        #pragma unroll
        for (int gg = 0; gg < 2; ++gg) {
            float p00 = ex2(s[2*gg][0] - nm0), p01 = ex2(s[2*gg][1] - nm0);
            float p02 = ex2(s[2*gg][2] - nm1), p03 = ex2(s[2*gg][3] - nm1);
            float p10 = ex2(s[2*gg+1][0] - nm0), p11 = ex2(s[2*gg+1][1] - nm0);
            float p12 = ex2(s[2*gg+1][2] - nm1), p13 = ex2(s[2*gg+1][3] - nm1);
            __half2 A0 = __floats2half2_rn(p00, p01);
            __half2 A1 = __floats2half2_rn(p02, p03);
            __half2 A2 = __floats2half2_rn(p10, p11);
            __half2 A3 = __floats2half2_rn(p12, p13);
            float2 f0 = __half22float2(A0), f1 = __half22float2(A1);
            float2 f2 = __half22float2(A2), f3 = __half22float2(A3);
            ps0 += f0.x + f0.y + f2.x + f2.y;
            ps1 += f1.x + f1.y + f3.x + f3.y;
            Apk[gg][0] = *(uint32_t*)&A0;
            Apk[gg][1] = *(uint32_t*)&A1;
            Apk[gg][2] = *(uint32_t*)&A2;
            Apk[gg][3] = *(uint32_t*)&A3;
        }
        l0 = l0 * cr0 + ps0;
        l1 = l1 * cr1 + ps1;

        if (__any_sync(0xffffffffu,
                       (__float_as_uint(cr0) != 0x3f800000u) |
                       (__float_as_uint(cr1) != 0x3f800000u))) {
            #pragma unroll
            for (int nd = 0; nd < 8; ++nd) {
                o[nd][0] *= cr0; o[nd][1] *= cr0;
                o[nd][2] *= cr1; o[nd][3] *= cr1;
            }
        }

        // ---- O_partial += P @ V over 32 keys (two k16 chunks) ----
        // ndp = 0 uses the preloaded fragments
        hmma16(o[0], Apk[0][0], Apk[0][1], Apk[0][2], Apk[0][3], vb0[0], vb0[1]);
        hmma16(o[1], Apk[0][0], Apk[0][1], Apk[0][2], Apk[0][3], vb0[2], vb0[3]);
        hmma16(o[0], Apk[1][0], Apk[1][1], Apk[1][2], Apk[1][3], vb1[0], vb1[1]);
        hmma16(o[1], Apk[1][0], Apk[1][1], Apk[1][2], Apk[1][3], vb1[2], vb1[3]);
        #pragma unroll
        for (int ndp = 1; ndp < 4; ++ndp) {
            uint32_t b0, b1, b2, b3;
            ldsm_x4(b0, b1, b2, b3, vtp + ndp * 16 * HS);
            hmma16(o[2 * ndp],     Apk[0][0], Apk[0][1], Apk[0][2], Apk[0][3], b0, b1);
            hmma16(o[2 * ndp + 1], Apk[0][0], Apk[0][1], Apk[0][2], Apk[0][3], b2, b3);
            ldsm_x4(b0, b1, b2, b3, vtp + ndp * 16 * HS + 16);
            hmma16(o[2 * ndp],     Apk[1][0], Apk[1][1], Apk[1][2], Apk[1][3], b0, b1);
            hmma16(o[2 * ndp + 1], Apk[1][0], Apk[1][1], Apk[1][2], Apk[1][3], b2, b3);
        }
    }

    // lane-reduce the deferred l partials (once)
    l0 += __shfl_xor_sync(0xffffffffu, l0, 1);
    l0 += __shfl_xor_sync(0xffffffffu, l0, 2);
    l1 += __shfl_xor_sync(0xffffffffu, l1, 1);
    l1 += __shfl_xor_sync(0xffffffffu, l1, 2);

    // ---- epilogue: merge 4 partials per row (2 groups x 2 key-halves) ----
    __syncthreads();   // full-CTA: both groups done with their buffers
    const int p = g * 2 + khalf;               // partial index 0..3
    float* R1 = (float*)(smb + QS_OFF);
    float* R2 = (float*)(smb + GB_OFF);
    float* R3 = (float*)(smb + GB_OFF + 16384);
    float* Rs[3] = { R1, R2, R3 };

    if (p > 0) {
        float* Rb = Rs[p - 1];
        if (lr == 0) {
            mA[(p - 1) * 64 + r0]     = m0;  mA[(p - 1) * 64 + r0 + 8] = m1;
            lA[(p - 1) * 64 + r0]     = l0;  lA[(p - 1) * 64 + r0 + 8] = l1;
        }
        #pragma unroll
        for (int nd = 0; nd < 8; ++nd) {
            *(float2*)&Rb[r0 * 64 + nd * 8 + 2 * lr]       = make_float2(o[nd][0], o[nd][1]);
            *(float2*)&Rb[(r0 + 8) * 64 + nd * 8 + 2 * lr] = make_float2(o[nd][2], o[nd][3]);
        }
    }
    __syncthreads();
    if (p == 0) {
        float M0 = m0, M1 = m1;
        #pragma unroll
        for (int i = 0; i < 3; ++i) {
            M0 = fmaxf(M0, mA[i * 64 + r0]);
            M1 = fmaxf(M1, mA[i * 64 + r0 + 8]);
        }
        float w0 = ex2(m0 - M0), w1 = ex2(m1 - M1);
        float L0 = l0 * w0, L1 = l1 * w1;
        float acc0[8][2], acc1[8][2];
        #pragma unroll
        for (int nd = 0; nd < 8; ++nd) {
            acc0[nd][0] = o[nd][0] * w0; acc0[nd][1] = o[nd][1] * w0;
            acc1[nd][0] = o[nd][2] * w1; acc1[nd][1] = o[nd][3] * w1;
        }
        #pragma unroll
        for (int i = 0; i < 3; ++i) {
            float u0 = ex2(mA[i * 64 + r0]     - M0);
            float u1 = ex2(mA[i * 64 + r0 + 8] - M1);
            L0 += lA[i * 64 + r0]     * u0;
            L1 += lA[i * 64 + r0 + 8] * u1;
            const float* Rb = Rs[i];
            #pragma unroll
            for (int nd = 0; nd < 8; ++nd) {
                float2 p0 = *(const float2*)&Rb[r0 * 64 + nd * 8 + 2 * lr];
                float2 p1 = *(const float2*)&Rb[(r0 + 8) * 64 + nd * 8 + 2 * lr];
                acc0[nd][0] += p0.x * u0; acc0[nd][1] += p0.y * u0;
                acc1[nd][0] += p1.x * u1; acc1[nd][1] += p1.y * u1;
            }
        }
        float il0 = 1.0f / L0, il1 = 1.0f / L1;
        int row = qrow0 + r0;
        #pragma unroll
        for (int nd = 0; nd < 8; ++nd) {
            *(float2*)&out[row * DOUT + nd * 8 + 2 * lr] =
                make_float2(acc0[nd][0] * il0, acc0[nd][1] * il0);
            *(float2*)&out[(row + 8) * DOUT + nd * 8 + 2 * lr] =
                make_float2(acc1[nd][0] * il1, acc1[nd][1] * il1);
        }
    }
}

// ---------------------------------------------------------------------------
extern "C" void kernel_launch(void* const* d_in, const int* in_sizes, int n_in,
                              void* d_out, int out_size)
{
    (void)in_sizes; (void)n_in; (void)out_size;
    const float* x  = (const float*)d_in[0];
    const float* wq = (const float*)d_in[1];
    const float* wk = (const float*)d_in[2];
    const float* wv = (const float*)d_in[3];
    float* out      = (float*)d_out;

    cudaFuncSetAttribute(proj_kernel,  cudaFuncAttributeMaxDynamicSharedMemorySize, PSM_TOTAL);
    cudaFuncSetAttribute(flash_kernel, cudaFuncAttributeMaxDynamicSharedMemorySize, SM_TOTAL);

    conv_kernel<<<24, 256>>>(wq, wk, wv);
    proj_kernel<<<dim3(SEQ / 64, 3), 256, PSM_TOTAL>>>(x);
    flash_kernel<<<SEQ / BM, 512, SM_TOTAL>>>(out);
}

// round 17
// speedup vs baseline: 1.1630x; 1.0806x over previous
#include <cuda_runtime.h>
#include <cuda_fp16.h>
#include <math.h>
#include <stdint.h>

#define SEQ  8192
#define DIN  512
#define DOUT 64

#define BM 64                  // Q rows per CTA (flash)
#define BN 64                  // keys per tile
#define NTG 64                 // tiles per group (128 total / 2 groups)
#define WQ 68                  // Q/x stage stride (floats)
#define HS 72                  // half-tile stride (halves) -> 144B, conflict-free

// (1/sqrt(64)) * log2(e) folded into Q
#define SCALE2 0.18033688011112042f

// flash smem layout (bytes)
#define QS_OFF   0                       // 64 x WQ floats = 17408
#define GB_OFF   17408
#define GKH(g,b) (GB_OFF + (g) * 55296 + (b) * 27648)
#define GKL(g,b) (GKH(g,b) + 9216)
#define GVT(g,b) (GKH(g,b) + 18432)
#define MA_OFF   128000                  // 192 floats
#define LA_OFF   128768                  // 192 floats
#define SM_TOTAL 129536

// proj smem layout (bytes): x fp32 [2], wh [2], wl [2]
#define PX_OFF(b) ((b) * 17408)          // 64 x WQ floats
#define PW_H(b)  (34816 + (b) * 9216)
#define PW_L(b)  (53248 + (b) * 9216)
#define PSM_TOTAL 71680

// ---------------- scratch ----------------
__device__ float  g_Q[SEQ * DOUT];
__device__ __half g_Kh[SEQ * DOUT];      // fp16 hi part of K  [seq][64]
__device__ __half g_Kl[SEQ * DOUT];      // fp16 lo part of K  [seq][64]
__device__ __half g_VT[DOUT * SEQ];      // fp16 V transposed  [d][seq]
__device__ __half g_WTh[3 * DOUT * DIN]; // fp16 hi of W^T [mat][n][k]
__device__ __half g_WTl[3 * DOUT * DIN]; // fp16 lo of W^T

// ---------------- helpers ----------------
__device__ __forceinline__ float ex2(float x) {
    float r;
    asm("ex2.approx.f32 %0, %1;" : "=f"(r) : "f"(x));
    return r;
}
__device__ __forceinline__ void hmma16(float d[4], uint32_t a0, uint32_t a1,
                                       uint32_t a2, uint32_t a3,
                                       uint32_t b0, uint32_t b1) {
    asm volatile(
        "mma.sync.aligned.m16n8k16.row.col.f32.f16.f16.f32 "
        "{%0,%1,%2,%3}, {%4,%5,%6,%7}, {%8,%9}, {%0,%1,%2,%3};"
        : "+f"(d[0]), "+f"(d[1]), "+f"(d[2]), "+f"(d[3])
        : "r"(a0), "r"(a1), "r"(a2), "r"(a3), "r"(b0), "r"(b1));
}
__device__ __forceinline__ void ldsm_x4(uint32_t& r0, uint32_t& r1,
                                        uint32_t& r2, uint32_t& r3,
                                        const void* p) {
    uint32_t a = (uint32_t)__cvta_generic_to_shared(p);
    asm volatile("ldmatrix.sync.aligned.m8n8.x4.shared.b16 {%0,%1,%2,%3}, [%4];"
                 : "=r"(r0), "=r"(r1), "=r"(r2), "=r"(r3) : "r"(a));
}
__device__ __forceinline__ void cp16(void* dst, const void* src) {
    uint32_t d = (uint32_t)__cvta_generic_to_shared(dst);
    asm volatile("cp.async.cg.shared.global [%0], [%1], 16;" :: "r"(d), "l"(src));
}
#define CP_COMMIT() asm volatile("cp.async.commit_group;" ::: "memory")
#define CP_WAIT(n)  asm volatile("cp.async.wait_group %0;" :: "n"(n) : "memory")
#define BAR_GRP(id) asm volatile("bar.sync %0, 256;" :: "r"(id) : "memory")

// split a pair of fp32 into packed hi/lo half2
__device__ __forceinline__ void pair_split(float x0, float x1,
                                           uint32_t& h, uint32_t& l) {
    __half2 hh = __floats2half2_rn(x0, x1);
    float2 hf = __half22float2(hh);
    __half2 ll = __floats2half2_rn(x0 - hf.x, x1 - hf.y);
    h = *(uint32_t*)&hh;
    l = *(uint32_t*)&ll;
}

// ---------------------------------------------------------------------------
// Kernel 0: W -> W^T (hi, lo) fp16 via smem transpose. grid=48 (32-row tiles).
// ---------------------------------------------------------------------------
__global__ __launch_bounds__(256)
void conv_kernel(const float* __restrict__ wq,
                 const float* __restrict__ wk,
                 const float* __restrict__ wv)
{
    __shared__ float ws[32 * 65];
    int wb  = blockIdx.x;                     // 0..47
    int mat = wb >> 4;
    int k0  = (wb & 15) * 32;
    const float* Wm = (mat == 0) ? wq : (mat == 1) ? wk : wv;

    // coalesced load of W[k0..k0+31][0..63] into smem (scalar stores, padded)
    #pragma unroll
    for (int it = 0; it < 2; ++it) {
        int idx = it * 256 + threadIdx.x;     // 0..511 float4 chunks
        int r = idx >> 4, c = idx & 15;
        float4 v = *(const float4*)&Wm[(k0 + r) * DOUT + c * 4];
        float* p = &ws[r * 65 + c * 4];
        p[0] = v.x; p[1] = v.y; p[2] = v.z; p[3] = v.w;
    }
    __syncthreads();

    // transpose out: thread handles row n, 8 k's
    int n = threadIdx.x >> 2, q = threadIdx.x & 3;
    __half hb[8], lb[8];
    #pragma unroll
    for (int j = 0; j < 8; ++j) {
        float v = ws[(q * 8 + j) * 65 + n];
        __half h = __float2half_rn(v);
        hb[j] = h;
        lb[j] = __float2half_rn(v - __half2float(h));
    }
    size_t off = (size_t)(mat * DOUT + n) * DIN + k0 + q * 8;
    *(int4*)&g_WTh[off] = *(int4*)&hb[0];
    *(int4*)&g_WTl[off] = *(int4*)&lb[0];
}

// ---------------------------------------------------------------------------
// Kernel 1: QKV projection, fp16 3-pass HMMA, x split inline, W via ldmatrix.
// grid=(128,3), block=256.
// ---------------------------------------------------------------------------
__device__ __forceinline__ void proj_load(char* smb, const float* x, int row0,
                                          int mat, int kc0, int b, int tid) {
    float*  xs = (float*)(smb + PX_OFF(b));
    __half* wh = (__half*)(smb + PW_H(b));
    __half* wl = (__half*)(smb + PW_L(b));
    const __half* wthg = g_WTh + (size_t)mat * DOUT * DIN;
    const __half* wtlg = g_WTl + (size_t)mat * DOUT * DIN;
    #pragma unroll
    for (int it = 0; it < 4; ++it) {
        int idx = it * 256 + tid;         // 0..1023 float4 chunks
        int r = idx >> 4, c4 = idx & 15;
        cp16(&xs[r * WQ + c4 * 4], &x[(size_t)(row0 + r) * DIN + kc0 + c4 * 4]);
    }
    #pragma unroll
    for (int it = 0; it < 2; ++it) {
        int idx = it * 256 + tid;         // 0..511
        int r = idx >> 3, c8 = idx & 7;
        cp16(&wh[r * HS + c8 * 8], &wthg[(size_t)r * DIN + kc0 + c8 * 8]);
        cp16(&wl[r * HS + c8 * 8], &wtlg[(size_t)r * DIN + kc0 + c8 * 8]);
    }
}

__global__ __launch_bounds__(256)
void proj_kernel(const float* __restrict__ x)
{
    extern __shared__ char smb[];
    const int tid   = threadIdx.x;
    const int lane  = tid & 31;
    const int wid   = tid >> 5;
    const int mrow  = wid & 3;
    const int nhalf = wid >> 2;
    const int lq    = lane >> 2;
    const int lr    = lane & 3;
    const int row0  = blockIdx.x * 64;
    const int mat   = blockIdx.y;
    const int r0    = mrow * 16 + lq;

    // ldmatrix lane offsets for W fragments (rows nhalf*32 .. +31)
    const int wOff0 = (nhalf * 32 + ((lane & 16) >> 1) + (lane & 7)) * HS + (lane & 8);
    const int wOff1 = wOff0 + 16 * HS;

    proj_load(smb, x, row0, mat, 0, 0, tid);
    CP_COMMIT();

    float acc[4][4] = {};

    #pragma unroll 1
    for (int c = 0; c < DIN / 64; ++c) {
        const int b = c & 1;
        CP_WAIT(0);
        __syncthreads();
        if (c + 1 < DIN / 64) {
            proj_load(smb, x, row0, mat, (c + 1) * 64, b ^ 1, tid);
            CP_COMMIT();
        }

        const float*  xs  = (const float*)(smb + PX_OFF(b));
        const __half* wh0 = (const __half*)(smb + PW_H(b)) + wOff0;
        const __half* wh1 = (const __half*)(smb + PW_H(b)) + wOff1;
        const __half* wl0 = (const __half*)(smb + PW_L(b)) + wOff0;
        const __half* wl1 = (const __half*)(smb + PW_L(b)) + wOff1;

        uint32_t ah[4][4], al[4][4];
        #pragma unroll
        for (int kc = 0; kc < 4; ++kc) {
            int cc = kc * 16 + 2 * lr;
            pair_split(xs[r0 * WQ + cc],           xs[r0 * WQ + cc + 1],
                       ah[kc][0], al[kc][0]);
            pair_split(xs[(r0 + 8) * WQ + cc],     xs[(r0 + 8) * WQ + cc + 1],
                       ah[kc][1], al[kc][1]);
            pair_split(xs[r0 * WQ + cc + 8],       xs[r0 * WQ + cc + 9],
                       ah[kc][2], al[kc][2]);
            pair_split(xs[(r0 + 8) * WQ + cc + 8], xs[(r0 + 8) * WQ + cc + 9],
                       ah[kc][3], al[kc][3]);
        }

        #pragma unroll
        for (int kc = 0; kc < 4; ++kc) {
            uint32_t b0, b1, b2, b3, c0, c1, c2, c3;
            ldsm_x4(b0, b1, b2, b3, wh0 + kc * 16);
            ldsm_x4(c0, c1, c2, c3, wl0 + kc * 16);
            hmma16(acc[0], ah[kc][0], ah[kc][1], ah[kc][2], ah[kc][3], b0, b1);
            hmma16(acc[0], al[kc][0], al[kc][1], al[kc][2], al[kc][3], b0, b1);
            hmma16(acc[0], ah[kc][0], ah[kc][1], ah[kc][2], ah[kc][3], c0, c1);
            hmma16(acc[1], ah[kc][0], ah[kc][1], ah[kc][2], ah[kc][3], b2, b3);
            hmma16(acc[1], al[kc][0], al[kc][1], al[kc][2], al[kc][3], b2, b3);
            hmma16(acc[1], ah[kc][0], ah[kc][1], ah[kc][2], ah[kc][3], c2, c3);

            ldsm_x4(b0, b1, b2, b3, wh1 + kc * 16);
            ldsm_x4(c0, c1, c2, c3, wl1 + kc * 16);
            hmma16(acc[2], ah[kc][0], ah[kc][1], ah[kc][2], ah[kc][3], b0, b1);
            hmma16(acc[2], al[kc][0], al[kc][1], al[kc][2], al[kc][3], b0, b1);
            hmma16(acc[2], ah[kc][0], ah[kc][1], ah[kc][2], ah[kc][3], c0, c1);
            hmma16(acc[3], ah[kc][0], ah[kc][1], ah[kc][2], ah[kc][3], b2, b3);
            hmma16(acc[3], al[kc][0], al[kc][1], al[kc][2], al[kc][3], b2, b3);
            hmma16(acc[3], ah[kc][0], ah[kc][1], ah[kc][2], ah[kc][3], c2, c3);
        }
    }

    const int rg = row0 + r0;
    if (mat == 0) {
        #pragma unroll
        for (int nt = 0; nt < 4; ++nt) {
            int cc = nhalf * 32 + nt * 8 + 2 * lr;
            *(float2*)&g_Q[(size_t)rg * DOUT + cc]       = make_float2(acc[nt][0], acc[nt][1]);
            *(float2*)&g_Q[(size_t)(rg + 8) * DOUT + cc] = make_float2(acc[nt][2], acc[nt][3]);
        }
    } else if (mat == 1) {
        #pragma unroll
        for (int nt = 0; nt < 4; ++nt) {
            int cc = nhalf * 32 + nt * 8 + 2 * lr;
            uint32_t h0, l0, h1, l1;
            pair_split(acc[nt][0], acc[nt][1], h0, l0);
            pair_split(acc[nt][2], acc[nt][3], h1, l1);
            *(uint32_t*)&g_Kh[(size_t)rg * DOUT + cc]       = h0;
            *(uint32_t*)&g_Kl[(size_t)rg * DOUT + cc]       = l0;
            *(uint32_t*)&g_Kh[(size_t)(rg + 8) * DOUT + cc] = h1;
            *(uint32_t*)&g_Kl[(size_t)(rg + 8) * DOUT + cc] = l1;
        }
    } else {
        #pragma unroll
        for (int nt = 0; nt < 4; ++nt) {
            int cc = nhalf * 32 + nt * 8 + 2 * lr;
            g_VT[(size_t)cc * SEQ + rg]           = __float2half_rn(acc[nt][0]);
            g_VT[(size_t)(cc + 1) * SEQ + rg]     = __float2half_rn(acc[nt][1]);
            g_VT[(size_t)cc * SEQ + rg + 8]       = __float2half_rn(acc[nt][2]);
            g_VT[(size_t)(cc + 1) * SEQ + rg + 8] = __float2half_rn(acc[nt][3]);
        }
    }
}

// ---------------------------------------------------------------------------
// Kernel 2: flash attention — R14/R16 structure; prefetch moved BELOW the
// S-MMA burst so the critical HMMA chain starts right after the barrier.
// ---------------------------------------------------------------------------
__device__ __forceinline__ void load_tile_g(char* smb, int tile, int g, int b,
                                            int gtid) {
    __half* kh = (__half*)(smb + GKH(g, b));
    __half* kl = (__half*)(smb + GKL(g, b));
    __half* vt = (__half*)(smb + GVT(g, b));
    #pragma unroll
    for (int i = 0; i < 2; ++i) {
        int idx = i * 256 + gtid;         // 0..511
        int r = idx >> 3, c8 = idx & 7;
        cp16(&kh[r * HS + c8 * 8], &g_Kh[(size_t)(tile * 64 + r) * DOUT + c8 * 8]);
        cp16(&kl[r * HS + c8 * 8], &g_Kl[(size_t)(tile * 64 + r) * DOUT + c8 * 8]);
        cp16(&vt[r * HS + c8 * 8], &g_VT[(size_t)r * SEQ + tile * 64 + c8 * 8]);
    }
}

__global__ __launch_bounds__(512, 1)
void flash_kernel(float* __restrict__ out)
{
    extern __shared__ char smb[];
    float* Qs = (float*)(smb + QS_OFF);
    float* mA = (float*)(smb + MA_OFF);
    float* lA = (float*)(smb + LA_OFF);

    const int tid   = threadIdx.x;
    const int lane  = tid & 31;
    const int wid   = tid >> 5;
    const int mrow  = wid & 3;
    const int khalf = (wid >> 2) & 1;
    const int g     = wid >> 3;           // warp group 0/1
    const int gtid  = tid & 255;
    const int kb    = khalf * 32;
    const int lq    = lane >> 2;
    const int lr    = lane & 3;
    const int qrow0 = blockIdx.x * BM;
    const int r0    = mrow * 16 + lq;

    // ldmatrix lane offsets (halves)
    const int sOff0 = (kb + ((lane & 16) >> 1) + (lane & 7)) * HS + (lane & 8);
    const int sOff1 = sOff0 + 16 * HS;
    const int vOff  = (((lane & 16) >> 1) + (lane & 7)) * HS + kb + (lane & 8);

    // group prefetch of its first tile
    load_tile_g(smb, g * NTG, g, 0, gtid);
    CP_COMMIT();

    // stage Q (whole CTA), build fragments
    #pragma unroll
    for (int i = 0; i < 2; ++i) {
        int idx = i * 512 + tid;
        int r = idx >> 4, c4 = idx & 15;
        *(float4*)&Qs[r * WQ + c4 * 4] = *(const float4*)&g_Q[(qrow0 + r) * DOUT + c4 * 4];
    }
    __syncthreads();

    uint32_t qh[4][4], ql[4][4];
    #pragma unroll
    for (int kc = 0; kc < 4; ++kc) {
        int c = kc * 16 + 2 * lr;
        pair_split(Qs[r0 * WQ + c] * SCALE2,           Qs[r0 * WQ + c + 1] * SCALE2,
                   qh[kc][0], ql[kc][0]);
        pair_split(Qs[(r0 + 8) * WQ + c] * SCALE2,     Qs[(r0 + 8) * WQ + c + 1] * SCALE2,
                   qh[kc][1], ql[kc][1]);
        pair_split(Qs[r0 * WQ + c + 8] * SCALE2,       Qs[r0 * WQ + c + 9] * SCALE2,
                   qh[kc][2], ql[kc][2]);
        pair_split(Qs[(r0 + 8) * WQ + c + 8] * SCALE2, Qs[(r0 + 8) * WQ + c + 9] * SCALE2,
                   qh[kc][3], ql[kc][3]);
    }

    float m0 = -INFINITY, m1 = -INFINITY;
    float l0 = 0.f, l1 = 0.f;              // lane-PARTIAL row sums
    float o[8][4];
    #pragma unroll
    for (int i = 0; i < 8; ++i)
        o[i][0] = o[i][1] = o[i][2] = o[i][3] = 0.f;

    #pragma unroll 1
    for (int tl = 0; tl < NTG; ++tl) {
        const int b = tl & 1;
        const __half* kh0 = (const __half*)(smb + GKH(g, b)) + sOff0;
        const __half* kl0 = (const __half*)(smb + GKL(g, b)) + sOff0;
        const __half* kh1 = (const __half*)(smb + GKH(g, b)) + sOff1;
        const __half* kl1 = (const __half*)(smb + GKL(g, b)) + sOff1;
        const __half* vtp = (const __half*)(smb + GVT(g, b)) + vOff;

        CP_WAIT(0);
        BAR_GRP(1 + g);

        // ---- S = Q K^T over this warp's 32 keys (two 16-key n-groups) ----
        float s[4][4] = {};
        #pragma unroll
        for (int kc = 0; kc < 4; ++kc) {
            uint32_t h0, h1, h2, h3, c0, c1, c2, c3;
            ldsm_x4(h0, h1, h2, h3, kh0 + kc * 16);
            ldsm_x4(c0, c1, c2, c3, kl0 + kc * 16);
            hmma16(s[0], qh[kc][0], qh[kc][1], qh[kc][2], qh[kc][3], h0, h1);
            hmma16(s[0], ql[kc][0], ql[kc][1], ql[kc][2], ql[kc][3], h0, h1);
            hmma16(s[0], qh[kc][0], qh[kc][1], qh[kc][2], qh[kc][3], c0, c1);
            hmma16(s[1], qh[kc][0], qh[kc][1], qh[kc][2], qh[kc][3], h2, h3);
            hmma16(s[1], ql[kc][0], ql[kc][1], ql[kc][2], ql[kc][3], h2, h3);
            hmma16(s[1], qh[kc][0], qh[kc][1], qh[kc][2], qh[kc][3], c2, c3);

            ldsm_x4(h0, h1, h2, h3, kh1 + kc * 16);
            ldsm_x4(c0, c1, c2, c3, kl1 + kc * 16);
            hmma16(s[2], qh[kc][0], qh[kc][1], qh[kc][2], qh[kc][3], h0, h1);
            hmma16(s[2], ql[kc][0], ql[kc][1], ql[kc][2], ql[kc][3], h0, h1);
            hmma16(s[2], qh[kc][0], qh[kc][1], qh[kc][2], qh[kc][3], c0, c1);
            hmma16(s[3], qh[kc][0], qh[kc][1], qh[kc][2], qh[kc][3], h2, h3);
            hmma16(s[3], ql[kc][0], ql[kc][1], ql[kc][2], ql[kc][3], h2, h3);
            hmma16(s[3], qh[kc][0], qh[kc][1], qh[kc][2], qh[kc][3], c2, c3);
        }

        // ---- preload first PV V-fragments (independent of softmax) ----
        uint32_t vb0[4], vb1[4];
        ldsm_x4(vb0[0], vb0[1], vb0[2], vb0[3], vtp);
        ldsm_x4(vb1[0], vb1[1], vb1[2], vb1[3], vtp + 16);

        // ---- prefetch next tile (now off the critical path) ----
        if (tl + 1 < NTG) {
            load_tile_g(smb, g * NTG + tl + 1, g, b ^ 1, gtid);
            CP_COMMIT();
        }

        // ---- warp-local online softmax over 32 keys ----
        float mx0 = fmaxf(fmaxf(s[0][0], s[0][1]), fmaxf(s[1][0], s[1][1]));
        float mx1 = fmaxf(fmaxf(s[0][2], s[0][3]), fmaxf(s[1][2], s[1][3]));
        mx0 = fmaxf(mx0, fmaxf(fmaxf(s[2][0], s[2][1]), fmaxf(s[3][0], s[3][1])));
        mx1 = fmaxf(mx1, fmaxf(fmaxf(s[2][2], s[2][3]), fmaxf(s[3][2], s[3][3])));
        mx0 = fmaxf(mx0, __shfl_xor_sync(0xffffffffu, mx0, 1));
        mx0 = fmaxf(mx0, __shfl_xor_sync(0xffffffffu, mx0, 2));
        mx1 = fmaxf(mx1, __shfl_xor_sync(0xffffffffu, mx1, 1));
        mx1 = fmaxf(mx1, __shfl_xor_sync(0xffffffffu, mx1, 2));

        float nm0 = fmaxf(m0, mx0), nm1 = fmaxf(m1, mx1);
        float cr0 = ex2(m0 - nm0),  cr1 = ex2(m1 - nm1);
        m0 = nm0; m1 = nm1;

        uint32_t Apk[2][4];
        float ps0 = 0.f, ps1 = 0.f;
        #pragma unroll
        for (int gg = 0; gg < 2; ++gg) {
            float p00 = ex2(s[2*gg][0] - nm0), p01 = ex2(s[2*gg][1] - nm0);
            float p02 = ex2(s[2*gg][2] - nm1), p03 = ex2(s[2*gg][3] - nm1);
            float p10 = ex2(s[2*gg+1][0] - nm0), p11 = ex2(s[2*gg+1][1] - nm0);
            float p12 = ex2(s[2*gg+1][2] - nm1), p13 = ex2(s[2*gg+1][3] - nm1);
            __half2 A0 = __floats2half2_rn(p00, p01);
            __half2 A1 = __floats2half2_rn(p02, p03);
            __half2 A2 = __floats2half2_rn(p10, p11);
            __half2 A3 = __floats2half2_rn(p12, p13);
            float2 f0 = __half22float2(A0), f1 = __half22float2(A1);
            float2 f2 = __half22float2(A2), f3 = __half22float2(A3);
            ps0 += f0.x + f0.y + f2.x + f2.y;
            ps1 += f1.x + f1.y + f3.x + f3.y;
            Apk[gg][0] = *(uint32_t*)&A0;
            Apk[gg][1] = *(uint32_t*)&A1;
            Apk[gg][2] = *(uint32_t*)&A2;
            Apk[gg][3] = *(uint32_t*)&A3;
        }
        l0 = l0 * cr0 + ps0;
        l1 = l1 * cr1 + ps1;

        if (__any_sync(0xffffffffu,
                       (__float_as_uint(cr0) != 0x3f800000u) |
                       (__float_as_uint(cr1) != 0x3f800000u))) {
            #pragma unroll
            for (int nd = 0; nd < 8; ++nd) {
                o[nd][0] *= cr0; o[nd][1] *= cr0;
                o[nd][2] *= cr1; o[nd][3] *= cr1;
            }
        }

        // ---- O_partial += P @ V over 32 keys (two k16 chunks) ----
        // ndp = 0 uses the preloaded fragments
        hmma16(o[0], Apk[0][0], Apk[0][1], Apk[0][2], Apk[0][3], vb0[0], vb0[1]);
        hmma16(o[1], Apk[0][0], Apk[0][1], Apk[0][2], Apk[0][3], vb0[2], vb0[3]);
        hmma16(o[0], Apk[1][0], Apk[1][1], Apk[1][2], Apk[1][3], vb1[0], vb1[1]);
        hmma16(o[1], Apk[1][0], Apk[1][1], Apk[1][2], Apk[1][3], vb1[2], vb1[3]);
        #pragma unroll
        for (int ndp = 1; ndp < 4; ++ndp) {
            uint32_t b0, b1, b2, b3;
            ldsm_x4(b0, b1, b2, b3, vtp + ndp * 16 * HS);
            hmma16(o[2 * ndp],     Apk[0][0], Apk[0][1], Apk[0][2], Apk[0][3], b0, b1);
            hmma16(o[2 * ndp + 1], Apk[0][0], Apk[0][1], Apk[0][2], Apk[0][3], b2, b3);
            ldsm_x4(b0, b1, b2, b3, vtp + ndp * 16 * HS + 16);
            hmma16(o[2 * ndp],     Apk[1][0], Apk[1][1], Apk[1][2], Apk[1][3], b0, b1);
            hmma16(o[2 * ndp + 1], Apk[1][0], Apk[1][1], Apk[1][2], Apk[1][3], b2, b3);
        }
    }

    // lane-reduce the deferred l partials (once)
    l0 += __shfl_xor_sync(0xffffffffu, l0, 1);
    l0 += __shfl_xor_sync(0xffffffffu, l0, 2);
    l1 += __shfl_xor_sync(0xffffffffu, l1, 1);
    l1 += __shfl_xor_sync(0xffffffffu, l1, 2);

    // ---- epilogue: merge 4 partials per row (2 groups x 2 key-halves) ----
    __syncthreads();   // full-CTA: both groups done with their buffers
    const int p = g * 2 + khalf;               // partial index 0..3
    float* R1 = (float*)(smb + QS_OFF);
    float* R2 = (float*)(smb + GB_OFF);
    float* R3 = (float*)(smb + GB_OFF + 16384);
    float* Rs[3] = { R1, R2, R3 };

    if (p > 0) {
        float* Rb = Rs[p - 1];
        if (lr == 0) {
            mA[(p - 1) * 64 + r0]     = m0;  mA[(p - 1) * 64 + r0 + 8] = m1;
            lA[(p - 1) * 64 + r0]     = l0;  lA[(p - 1) * 64 + r0 + 8] = l1;
        }
        #pragma unroll
        for (int nd = 0; nd < 8; ++nd) {
            *(float2*)&Rb[r0 * 64 + nd * 8 + 2 * lr]       = make_float2(o[nd][0], o[nd][1]);
            *(float2*)&Rb[(r0 + 8) * 64 + nd * 8 + 2 * lr] = make_float2(o[nd][2], o[nd][3]);
        }
    }
    __syncthreads();
    if (p == 0) {
        float M0 = m0, M1 = m1;
        #pragma unroll
        for (int i = 0; i < 3; ++i) {
            M0 = fmaxf(M0, mA[i * 64 + r0]);
            M1 = fmaxf(M1, mA[i * 64 + r0 + 8]);
        }
        float w0 = ex2(m0 - M0), w1 = ex2(m1 - M1);
        float L0 = l0 * w0, L1 = l1 * w1;
        float acc0[8][2], acc1[8][2];
        #pragma unroll
        for (int nd = 0; nd < 8; ++nd) {
            acc0[nd][0] = o[nd][0] * w0; acc0[nd][1] = o[nd][1] * w0;
            acc1[nd][0] = o[nd][2] * w1; acc1[nd][1] = o[nd][3] * w1;
        }
        #pragma unroll
        for (int i = 0; i < 3; ++i) {
            float u0 = ex2(mA[i * 64 + r0]     - M0);
            float u1 = ex2(mA[i * 64 + r0 + 8] - M1);
            L0 += lA[i * 64 + r0]     * u0;
            L1 += lA[i * 64 + r0 + 8] * u1;
            const float* Rb = Rs[i];
            #pragma unroll
            for (int nd = 0; nd < 8; ++nd) {
                float2 p0 = *(const float2*)&Rb[r0 * 64 + nd * 8 + 2 * lr];
                float2 p1 = *(const float2*)&Rb[(r0 + 8) * 64 + nd * 8 + 2 * lr];
                acc0[nd][0] += p0.x * u0; acc0[nd][1] += p0.y * u0;
                acc1[nd][0] += p1.x * u1; acc1[nd][1] += p1.y * u1;
            }
        }
        float il0 = 1.0f / L0, il1 = 1.0f / L1;
        int row = qrow0 + r0;
        #pragma unroll
        for (int nd = 0; nd < 8; ++nd) {
            *(float2*)&out[row * DOUT + nd * 8 + 2 * lr] =
                make_float2(acc0[nd][0] * il0, acc0[nd][1] * il0);
            *(float2*)&out[(row + 8) * DOUT + nd * 8 + 2 * lr] =
                make_float2(acc1[nd][0] * il1, acc1[nd][1] * il1);
        }
    }
}

// ---------------------------------------------------------------------------
extern "C" void kernel_launch(void* const* d_in, const int* in_sizes, int n_in,
                              void* d_out, int out_size)
{
    (void)in_sizes; (void)n_in; (void)out_size;
    const float* x  = (const float*)d_in[0];
    const float* wq = (const float*)d_in[1];
    const float* wk = (const float*)d_in[2];
    const float* wv = (const float*)d_in[3];
    float* out      = (float*)d_out;

    cudaFuncSetAttribute(proj_kernel,  cudaFuncAttributeMaxDynamicSharedMemorySize, PSM_TOTAL);
    cudaFuncSetAttribute(flash_kernel, cudaFuncAttributeMaxDynamicSharedMemorySize, SM_TOTAL);

    conv_kernel<<<48, 256>>>(wq, wk, wv);
    proj_kernel<<<dim3(SEQ / 64, 3), 256, PSM_TOTAL>>>(x);
    flash_kernel<<<SEQ / BM, 512, SM_TOTAL>>>(out);
}